// round 14
// baseline (speedup 1.0000x reference)
#include <cuda_runtime.h>
#include <cuda_fp16.h>
#include <cstdint>
#include <math.h>

#define B_   256
#define T_   512
#define D_   128
#define H_   1024
#define G_   3072
#define O_   128
#define DIN  257
#define KIN  320

// ---- persistent kernel smem ----
#define WCH     12288                  // one k-chunk of W: 96 rows x 128B
#define W_SM    (16 * WCH)             // 196608
#define AST     8192                   // A stage: 64 rows x 128B
#define P_SMEM  (W_SM + 4 * AST)       // 229376

// ---- gi kernel smem ----
#define GI_WSM   (5 * WCH)             // 61440 (K=320 -> 5 chunks)
#define GI_SMEM2 (GI_WSM + 4 * AST)    // 94208  -> 2 CTAs/SM
#define M_REP    8
#define GI_NSTG  (M_REP * 5)

// ---------------- scratch ----------------
__device__ __half g_gi[(size_t)T_ * B_ * G_];     // fp16 gi (+ folded biases)
__device__ __half g_xh[(size_t)(T_ * B_) * KIN];
__device__ __half g_wih[(size_t)G_ * KIN];
__device__ __half g_w3[(size_t)G_ * H_];
__device__ float  g_hf[2][B_ * H_];
__device__ __half g_hh[2][B_ * H_];
__device__ unsigned g_bars[64];

// ---------------- helpers ----------------
__device__ __forceinline__ float fsig(float x) {
    float e; asm("ex2.approx.f32 %0, %1;" : "=f"(e) : "f"(-1.4426950408889634f * x));
    float r; asm("rcp.approx.f32 %0, %1;" : "=f"(r) : "f"(1.0f + e));
    return r;
}
__device__ __forceinline__ float ftanh_(float x) {
    float e; asm("ex2.approx.f32 %0, %1;" : "=f"(e) : "f"(-2.8853900817779268f * x));
    float r; asm("rcp.approx.f32 %0, %1;" : "=f"(r) : "f"(1.0f + e));
    return 2.0f * r - 1.0f;
}
__device__ __forceinline__ uint32_t smem_u32(const void* p) {
    uint32_t a; asm("{ .reg .u64 t; cvta.to.shared.u64 t, %1; cvt.u32.u64 %0, t; }" : "=r"(a) : "l"(p)); return a;
}
__device__ __forceinline__ void cpa16(uint32_t d, const void* s) {
    asm volatile("cp.async.cg.shared.global [%0], [%1], 16;" :: "r"(d), "l"(s));
}
__device__ __forceinline__ void cpcommit() { asm volatile("cp.async.commit_group;"); }
__device__ __forceinline__ void cpwait2()  { asm volatile("cp.async.wait_group 2;" ::: "memory"); }
__device__ __forceinline__ void cpwait0()  { asm volatile("cp.async.wait_group 0;" ::: "memory"); }

#define LDSM4(r0, r1, r2, r3, addr) \
    asm volatile("ldmatrix.sync.aligned.m8n8.x4.shared.b16 {%0,%1,%2,%3}, [%4];" \
        : "=r"(r0), "=r"(r1), "=r"(r2), "=r"(r3) : "r"(addr))
#define LDSM2(r0, r1, addr) \
    asm volatile("ldmatrix.sync.aligned.m8n8.x2.shared.b16 {%0,%1}, [%2];" \
        : "=r"(r0), "=r"(r1) : "r"(addr))

__device__ __forceinline__ void mma_f16(float* d, uint32_t a0, uint32_t a1, uint32_t a2, uint32_t a3,
                                        uint32_t b0, uint32_t b1) {
    asm volatile("mma.sync.aligned.m16n8k16.row.col.f32.f16.f16.f32 "
        "{%0,%1,%2,%3},{%4,%5,%6,%7},{%8,%9},{%0,%1,%2,%3};\n"
        : "+f"(d[0]), "+f"(d[1]), "+f"(d[2]), "+f"(d[3])
        : "r"(a0), "r"(a1), "r"(a2), "r"(a3), "r"(b0), "r"(b1));
}

// ---------------- fused pack kernel ----------------
#define NBX  163840
#define NBW3 12288
#define NBW  3840
#define NBZ  1024
__global__ void pack_fused(const float* __restrict__ x, const float* __restrict__ mask,
                           const float* __restrict__ ti, const float* __restrict__ W_ih,
                           const float* __restrict__ W_hh) {
    long long bid = blockIdx.x;
    int tidl = threadIdx.x;
    if (bid < NBX) {
        size_t idx = (size_t)bid * 256 + tidl;
        int k = (int)(idx % KIN);
        size_t row = idx / KIN;
        int t = (int)(row >> 8), b = (int)(row & 255);
        float v = 0.f;
        if (k < 128) v = x[((size_t)b * T_ + t) * D_ + k];
        else if (k < 256) v = mask[((size_t)b * T_ + t) * D_ + (k - 128)];
        else if (k == 256) v = ti[(size_t)b * T_ + t];
        g_xh[idx] = __float2half_rn(v);
    } else if (bid < NBX + NBW3) {
        size_t idx = (size_t)(bid - NBX) * 256 + tidl;
        g_w3[idx] = __float2half_rn(W_hh[idx]);
    } else if (bid < NBX + NBW3 + NBW) {
        size_t idx = (size_t)(bid - NBX - NBW3) * 256 + tidl;
        int k = (int)(idx % KIN); size_t g = idx / KIN;
        g_wih[idx] = (k < DIN) ? __float2half_rn(W_ih[g * DIN + k]) : __float2half_rn(0.0f);
    } else {
        size_t idx = (size_t)(bid - NBX - NBW3 - NBW) * 256 + tidl;
        if (idx < B_ * H_) { g_hf[0][idx] = 0.0f; g_hh[0][idx] = __float2half_rn(0.0f); }
        if (idx < 64) g_bars[idx] = 0u;
    }
}
__global__ void bar_zero() { if (threadIdx.x < 64) g_bars[threadIdx.x] = 0u; }

// ---------------- gi GEMM: W_ih-resident, x = n-slice, y = m-block (A L2 reuse) ----------------
__global__ __launch_bounds__(256, 2) void gi_gemm4(const float* __restrict__ b_ih,
                                                   const float* __restrict__ b_hh) {
    extern __shared__ char smc[];
    uint32_t sb = smem_u32(smc);
    uint32_t ast = sb + GI_WSM;
    const int tid = threadIdx.x, lane = tid & 31, wid = tid >> 5;
    const int wm = (wid >> 2) * 32;
    const int wn8 = (wid & 3) * 8;
    const int g4 = lane >> 2, tig = lane & 3;
    const int ni = blockIdx.x, n0 = ni * 32;
    const size_t mbase = (size_t)blockIdx.y * (M_REP * 64);

    // ---- load W_ih slice (5 chunks x 96 rows x 128B, swizzled) ----
    {
#pragma unroll 1
        for (int i = tid; i < 5 * 96 * 8; i += 256) {
            int chunk = i / 768, rem = i % 768;
            int rr = rem >> 3, c = rem & 7;
            int grow = (rr >> 5) * H_ + n0 + (rr & 31);
            uint32_t dst = sb + (uint32_t)(chunk * WCH + rr * 128 + ((c ^ (rr & 7)) << 4));
            cpa16(dst, g_wih + (size_t)grow * KIN + chunk * 64 + c * 8);
        }
        cpcommit(); cpwait0();
        __syncthreads();
    }

    const int arow0 = wm + (lane & 15);
    const int acsel = (lane >> 4);
    const int browA = ((lane < 16) ? 0 : 32) + wn8 + (lane & 7);
    const int browC = 64 + wn8 + (lane & 7);
    const int bcsel = (lane >> 3) & 1;

    const int gcol = n0 + wn8 + 2 * tig;
    float2 biasr = { b_ih[gcol] + b_hh[gcol], b_ih[gcol + 1] + b_hh[gcol + 1] };
    float2 biasz = { b_ih[H_ + gcol] + b_hh[H_ + gcol], b_ih[H_ + gcol + 1] + b_hh[H_ + gcol + 1] };
    float2 biasn = { b_ih[2 * H_ + gcol], b_ih[2 * H_ + gcol + 1] };

    auto issueA = [&](int s) {
        int rep = s / 5, chunk = s - rep * 5;
        uint32_t ab = ast + (uint32_t)((s & 3) * AST);
        const __half* Ag = g_xh + (mbase + (size_t)rep * 64) * KIN + chunk * 64;
#pragma unroll
        for (int i = 0; i < 2; i++) {
            int f = tid + 256 * i, r = f >> 3, c = f & 7;
            cpa16(ab + (uint32_t)(r * 128 + ((c ^ (r & 7)) << 4)),
                  Ag + (size_t)r * KIN + c * 8);
        }
        cpcommit();
    };

    float acc[2][3][4];
#pragma unroll
    for (int i = 0; i < 2; i++)
#pragma unroll
        for (int j = 0; j < 3; j++)
#pragma unroll
            for (int e = 0; e < 4; e++) acc[i][j][e] = 0.f;

    issueA(0); issueA(1); issueA(2);
#pragma unroll 1
    for (int s = 0; s < GI_NSTG; s++) {
        cpwait2();
        __syncthreads();
        int rep = s / 5, chunk = s - rep * 5;
        uint32_t ab = ast + (uint32_t)((s & 3) * AST);
        uint32_t wb = sb + (uint32_t)(chunk * WCH);
#pragma unroll
        for (int g = 0; g < 4; g++) {
            uint32_t A0[4], A1[4], B4[4], B2[2];
            {
                int c = 2 * g + acsel;
                int r0 = arow0, r1 = arow0 + 16;
                LDSM4(A0[0], A0[1], A0[2], A0[3], ab + (uint32_t)(r0 * 128 + ((c ^ (r0 & 7)) << 4)));
                LDSM4(A1[0], A1[1], A1[2], A1[3], ab + (uint32_t)(r1 * 128 + ((c ^ (r1 & 7)) << 4)));
            }
            {
                int c = 2 * g + bcsel;
                LDSM4(B4[0], B4[1], B4[2], B4[3], wb + (uint32_t)(browA * 128 + ((c ^ (browA & 7)) << 4)));
                LDSM2(B2[0], B2[1], wb + (uint32_t)(browC * 128 + ((c ^ (browC & 7)) << 4)));
            }
            mma_f16(acc[0][0], A0[0], A0[1], A0[2], A0[3], B4[0], B4[1]);
            mma_f16(acc[1][0], A1[0], A1[1], A1[2], A1[3], B4[0], B4[1]);
            mma_f16(acc[0][1], A0[0], A0[1], A0[2], A0[3], B4[2], B4[3]);
            mma_f16(acc[1][1], A1[0], A1[1], A1[2], A1[3], B4[2], B4[3]);
            mma_f16(acc[0][2], A0[0], A0[1], A0[2], A0[3], B2[0], B2[1]);
            mma_f16(acc[1][2], A1[0], A1[1], A1[2], A1[3], B2[0], B2[1]);
        }
        if (s + 3 < GI_NSTG) issueA(s + 3); else cpcommit();

        if (chunk == 4) {
            size_t rowbase = mbase + (size_t)rep * 64;
#pragma unroll
            for (int mt = 0; mt < 2; mt++)
#pragma unroll
                for (int rh = 0; rh < 2; rh++) {
                    size_t row = rowbase + wm + mt * 16 + g4 + 8 * rh;
                    __half* gp = g_gi + row * G_ + gcol;
                    *(__half2*)(gp)          = __floats2half2_rn(acc[mt][0][2 * rh] + biasr.x,
                                                                 acc[mt][0][2 * rh + 1] + biasr.y);
                    *(__half2*)(gp + H_)     = __floats2half2_rn(acc[mt][1][2 * rh] + biasz.x,
                                                                 acc[mt][1][2 * rh + 1] + biasz.y);
                    *(__half2*)(gp + 2 * H_) = __floats2half2_rn(acc[mt][2][2 * rh] + biasn.x,
                                                                 acc[mt][2][2 * rh + 1] + biasn.y);
                }
#pragma unroll
            for (int i = 0; i < 2; i++)
#pragma unroll
                for (int j = 0; j < 3; j++)
#pragma unroll
                    for (int e = 0; e < 4; e++) acc[i][j][e] = 0.f;
        }
    }
    cpwait0();
}

// ---------------- persistent GRU recurrence (warp-granular barrier) ----------------
// Arrivals: 8 warps x 32 CTAs = 256 per group per step. Consumer warps spin independently.
__global__ __launch_bounds__(256, 1) void gru_persist() {
    extern __shared__ char smc[];
    uint32_t sb = smem_u32(smc);
    uint32_t ast = sb + W_SM;
    const int tid = threadIdx.x, lane = tid & 31, wid = tid >> 5;
    const int wm = (wid >> 2) * 32;
    const int wn8 = (wid & 3) * 8;
    const int g4 = lane >> 2, tig = lane & 3;
    const int mi = blockIdx.x >> 5, ni = blockIdx.x & 31;
    const int m0 = mi * 64, n0 = ni * 32;
    unsigned* barp = &g_bars[mi * 16];

    // ---- load W_hh slice once ----
    {
#pragma unroll 1
        for (int i = tid; i < 12288; i += 256) {
            int rr = i >> 7, cg = i & 127;
            int s = cg >> 3, c = cg & 7;
            int grow = (rr >> 5) * H_ + n0 + (rr & 31);
            uint32_t dst = sb + (uint32_t)(s * WCH + rr * 128 + ((c ^ (rr & 7)) << 4));
            cpa16(dst, g_w3 + (size_t)grow * H_ + s * 64 + c * 8);
        }
        cpcommit(); cpwait0();
        __syncthreads();
    }

    const int arow0 = wm + (lane & 15);
    const int acsel = (lane >> 4);
    const int browA = ((lane < 16) ? 0 : 32) + wn8 + (lane & 7);
    const int browC = 64 + wn8 + (lane & 7);
    const int bcsel = (lane >> 3) & 1;

    const int col2 = n0 + wn8 + 2 * tig;

    // register-carried h; h0 = 0
    float hc[8];
#pragma unroll
    for (int j = 0; j < 8; j++) hc[j] = 0.f;

    // gi prefetch for t=0 (fp16)
    float2 gir[4], giz[4], gin[4];
#pragma unroll
    for (int q = 0; q < 4; q++) {
        int row = m0 + wm + (q >> 1) * 16 + g4 + 8 * (q & 1);
        const __half* p = g_gi + (size_t)row * G_ + col2;
        gir[q] = __half22float2(*(const __half2*)(p));
        giz[q] = __half22float2(*(const __half2*)(p + H_));
        gin[q] = __half22float2(*(const __half2*)(p + 2 * H_));
    }

#pragma unroll 1
    for (int t = 0; t < T_; t++) {
        // ---- warp-granular wait for h(t): 256 arrivals per prior step ----
        if (t > 0) {
            if (lane == 0) {
                unsigned v; const unsigned tgt = 256u * (unsigned)t;
                do { asm volatile("ld.acquire.gpu.global.u32 %0, [%1];" : "=r"(v) : "l"(barp)); } while (v < tgt);
            }
            __syncwarp();
        }

        const __half* __restrict__ Ah = g_hh[t & 1] + (size_t)m0 * H_;

        float acc[2][3][4];
#pragma unroll
        for (int i = 0; i < 2; i++)
#pragma unroll
            for (int j = 0; j < 3; j++)
#pragma unroll
                for (int e = 0; e < 4; e++) acc[i][j][e] = 0.f;

        auto issueA = [&](int s) {
            int buf = s & 3;
            uint32_t ab = ast + (uint32_t)(buf * AST);
            int kc = s * 64;
#pragma unroll
            for (int i = 0; i < 2; i++) {
                int f = tid + 256 * i, r = f >> 3, c = f & 7;
                cpa16(ab + (uint32_t)(r * 128 + ((c ^ (r & 7)) << 4)),
                      Ah + (size_t)r * H_ + kc + c * 8);
            }
            cpcommit();
        };
        issueA(0); issueA(1); issueA(2);
#pragma unroll 1
        for (int s = 0; s < 16; s++) {
            cpwait2();
            __syncthreads();
            uint32_t ab = ast + (uint32_t)((s & 3) * AST);
            uint32_t wb = sb + (uint32_t)(s * WCH);
#pragma unroll
            for (int g = 0; g < 4; g++) {
                uint32_t A0[4], A1[4], B4[4], B2[2];
                {
                    int c = 2 * g + acsel;
                    int r0 = arow0, r1 = arow0 + 16;
                    LDSM4(A0[0], A0[1], A0[2], A0[3], ab + (uint32_t)(r0 * 128 + ((c ^ (r0 & 7)) << 4)));
                    LDSM4(A1[0], A1[1], A1[2], A1[3], ab + (uint32_t)(r1 * 128 + ((c ^ (r1 & 7)) << 4)));
                }
                {
                    int c = 2 * g + bcsel;
                    LDSM4(B4[0], B4[1], B4[2], B4[3], wb + (uint32_t)(browA * 128 + ((c ^ (browA & 7)) << 4)));
                    LDSM2(B2[0], B2[1], wb + (uint32_t)(browC * 128 + ((c ^ (browC & 7)) << 4)));
                }
                mma_f16(acc[0][0], A0[0], A0[1], A0[2], A0[3], B4[0], B4[1]);
                mma_f16(acc[1][0], A1[0], A1[1], A1[2], A1[3], B4[0], B4[1]);
                mma_f16(acc[0][1], A0[0], A0[1], A0[2], A0[3], B4[2], B4[3]);
                mma_f16(acc[1][1], A1[0], A1[1], A1[2], A1[3], B4[2], B4[3]);
                mma_f16(acc[0][2], A0[0], A0[1], A0[2], A0[3], B2[0], B2[1]);
                mma_f16(acc[1][2], A1[0], A1[1], A1[2], A1[3], B2[0], B2[1]);
            }
            if (s + 3 < 16) issueA(s + 3); else cpcommit();
        }
        cpwait0();

        // ---- register-resident gate epilogue (n-gate b_hh folded into gi at pack) ----
        {
            __half* __restrict__ hxB = g_hh[(t + 1) & 1];
#pragma unroll
            for (int q = 0; q < 4; q++) {
                int mt = q >> 1, rh = q & 1;
                int row = m0 + wm + mt * 16 + g4 + 8 * rh;
                float o0, o1;
                {
                    float rr = fsig(gir[q].x + acc[mt][0][2 * rh]);
                    float zz = fsig(giz[q].x + acc[mt][1][2 * rh]);
                    float nn = ftanh_(gin[q].x + rr * acc[mt][2][2 * rh]);
                    o0 = (1.0f - zz) * nn + zz * hc[2 * q];
                }
                {
                    float rr = fsig(gir[q].y + acc[mt][0][2 * rh + 1]);
                    float zz = fsig(giz[q].y + acc[mt][1][2 * rh + 1]);
                    float nn = ftanh_(gin[q].y + rr * acc[mt][2][2 * rh + 1]);
                    o1 = (1.0f - zz) * nn + zz * hc[2 * q + 1];
                }
                hc[2 * q] = o0; hc[2 * q + 1] = o1;
                *(__half2*)(hxB + (size_t)row * H_ + col2) = __floats2half2_rn(o0, o1);
                if (t == T_ - 1) {
                    float2 ov = { o0, o1 };
                    *(float2*)(g_hf[0] + (size_t)row * H_ + col2) = ov;
                }
            }
        }

        // ---- warp-granular publish: this warp's stores done -> arrive ----
        __syncwarp();
        if (lane == 0)
            asm volatile("red.release.gpu.global.add.u32 [%0], 1;" :: "l"(barp) : "memory");

        // ---- prefetch gi(t+1) after arriving ----
        if (t + 1 < T_) {
            const __half* __restrict__ gi_t = g_gi + (size_t)(t + 1) * B_ * G_;
#pragma unroll
            for (int q = 0; q < 4; q++) {
                int row = m0 + wm + (q >> 1) * 16 + g4 + 8 * (q & 1);
                const __half* p = gi_t + (size_t)row * G_ + col2;
                gir[q] = __half22float2(*(const __half2*)(p));
                giz[q] = __half22float2(*(const __half2*)(p + H_));
                gin[q] = __half22float2(*(const __half2*)(p + 2 * H_));
            }
        }
    }
}

// ---------------- output head ----------------
__global__ void out_gemm(const float* __restrict__ Wout, const float* __restrict__ bout, float* __restrict__ out) {
    const int b = blockIdx.x;
    const int wid = threadIdx.x >> 5, lane = threadIdx.x & 31;
    const int o0 = blockIdx.y * 32 + wid * 4;
    const float* __restrict__ h = g_hf[0] + (size_t)b * H_;
    float acc[4] = {0.f, 0.f, 0.f, 0.f};
#pragma unroll
    for (int kk = 0; kk < 8; kk++) {
        int k = kk * 128 + lane * 4;
        float4 hv = *(const float4*)(h + k);
#pragma unroll
        for (int j = 0; j < 4; j++) {
            float4 w = *(const float4*)(Wout + (size_t)(o0 + j) * H_ + k);
            acc[j] += hv.x * w.x + hv.y * w.y + hv.z * w.z + hv.w * w.w;
        }
    }
#pragma unroll
    for (int j = 0; j < 4; j++) {
        float v = acc[j];
#pragma unroll
        for (int s = 16; s > 0; s >>= 1) v += __shfl_xor_sync(0xffffffffu, v, s);
        if (lane == 0) out[(size_t)b * O_ + o0 + j] = v + bout[o0 + j];
    }
}

// ---------------- launch ----------------
extern "C" void kernel_launch(void* const* d_in, const int* in_sizes, int n_in,
                              void* d_out, int out_size) {
    const float* x     = (const float*)d_in[0];
    const float* mask  = (const float*)d_in[1];
    const float* ti    = (const float*)d_in[2];
    const float* W_ih  = (const float*)d_in[3];
    const float* W_hh  = (const float*)d_in[4];
    const float* b_ih  = (const float*)d_in[5];
    const float* b_hh  = (const float*)d_in[6];
    const float* W_out = (const float*)d_in[7];
    const float* b_out = (const float*)d_in[8];
    float* out = (float*)d_out;

    static int smem_set = 0;
    if (!smem_set) {
        cudaFuncSetAttribute(gi_gemm4, cudaFuncAttributeMaxDynamicSharedMemorySize, GI_SMEM2);
        cudaFuncSetAttribute(gru_persist, cudaFuncAttributeMaxDynamicSharedMemorySize, P_SMEM);
        smem_set = 1;
    }

    pack_fused<<<NBX + NBW3 + NBW + NBZ, 256>>>(x, mask, ti, W_ih, W_hh);         // 0
    gi_gemm4<<<dim3(32, (T_ * B_) / (M_REP * 64)), 256, GI_SMEM2>>>(b_ih, b_hh);  // 1
    bar_zero<<<1, 64>>>();                                                         // 2
    gru_persist<<<128, 256, P_SMEM>>>();                                           // 3 (profiled)
    out_gemm<<<dim3(B_, O_ / 32), 256>>>(W_out, b_out, out);                       // 4
}

// round 15
// speedup vs baseline: 1.0684x; 1.0684x over previous
#include <cuda_runtime.h>
#include <cuda_fp16.h>
#include <cstdint>
#include <math.h>

#define B_   256
#define T_   512
#define D_   128
#define H_   1024
#define G_   3072
#define O_   128
#define DIN  257
#define KIN  320

// ---- persistent kernel smem ----
#define WCH     12288                  // one k-chunk of W: 96 rows x 128B
#define W_SM    (16 * WCH)             // 196608
#define AST     8192                   // A stage: 64 rows x 128B
#define P_SMEM  (W_SM + 4 * AST)       // 229376

// ---- gi kernel smem ----
#define GI_WSM   (5 * WCH)             // 61440 (K=320 -> 5 chunks)
#define GI_SMEM2 (GI_WSM + 4 * AST)    // 94208  -> 2 CTAs/SM
#define M_REP    8
#define GI_NSTG  (M_REP * 5)

// ---------------- scratch ----------------
__device__ __half g_gi[(size_t)T_ * B_ * G_];     // fp16 gi (+ folded biases)
__device__ __half g_xh[(size_t)(T_ * B_) * KIN];
__device__ __half g_wih[(size_t)G_ * KIN];
__device__ __half g_w3[(size_t)G_ * H_];
__device__ float  g_hf[2][B_ * H_];
__device__ __half g_hh[2][B_ * H_];
__device__ unsigned g_bars[64];

// ---------------- helpers ----------------
__device__ __forceinline__ float fsig(float x) {
    float e; asm("ex2.approx.f32 %0, %1;" : "=f"(e) : "f"(-1.4426950408889634f * x));
    float r; asm("rcp.approx.f32 %0, %1;" : "=f"(r) : "f"(1.0f + e));
    return r;
}
__device__ __forceinline__ float ftanh_(float x) {
    float e; asm("ex2.approx.f32 %0, %1;" : "=f"(e) : "f"(-2.8853900817779268f * x));
    float r; asm("rcp.approx.f32 %0, %1;" : "=f"(r) : "f"(1.0f + e));
    return 2.0f * r - 1.0f;
}
__device__ __forceinline__ uint32_t smem_u32(const void* p) {
    uint32_t a; asm("{ .reg .u64 t; cvta.to.shared.u64 t, %1; cvt.u32.u64 %0, t; }" : "=r"(a) : "l"(p)); return a;
}
__device__ __forceinline__ void cpa16(uint32_t d, const void* s) {
    asm volatile("cp.async.cg.shared.global [%0], [%1], 16;" :: "r"(d), "l"(s));
}
__device__ __forceinline__ void cpcommit() { asm volatile("cp.async.commit_group;"); }
__device__ __forceinline__ void cpwait2()  { asm volatile("cp.async.wait_group 2;" ::: "memory"); }
__device__ __forceinline__ void cpwait0()  { asm volatile("cp.async.wait_group 0;" ::: "memory"); }

#define LDSM4(r0, r1, r2, r3, addr) \
    asm volatile("ldmatrix.sync.aligned.m8n8.x4.shared.b16 {%0,%1,%2,%3}, [%4];" \
        : "=r"(r0), "=r"(r1), "=r"(r2), "=r"(r3) : "r"(addr))
#define LDSM2(r0, r1, addr) \
    asm volatile("ldmatrix.sync.aligned.m8n8.x2.shared.b16 {%0,%1}, [%2];" \
        : "=r"(r0), "=r"(r1) : "r"(addr))

__device__ __forceinline__ void mma_f16(float* d, uint32_t a0, uint32_t a1, uint32_t a2, uint32_t a3,
                                        uint32_t b0, uint32_t b1) {
    asm volatile("mma.sync.aligned.m16n8k16.row.col.f32.f16.f16.f32 "
        "{%0,%1,%2,%3},{%4,%5,%6,%7},{%8,%9},{%0,%1,%2,%3};\n"
        : "+f"(d[0]), "+f"(d[1]), "+f"(d[2]), "+f"(d[3])
        : "r"(a0), "r"(a1), "r"(a2), "r"(a3), "r"(b0), "r"(b1));
}

// ---------------- fused pack kernel ----------------
#define NBX  163840
#define NBW3 12288
#define NBW  3840
#define NBZ  1024
__global__ void pack_fused(const float* __restrict__ x, const float* __restrict__ mask,
                           const float* __restrict__ ti, const float* __restrict__ W_ih,
                           const float* __restrict__ W_hh) {
    long long bid = blockIdx.x;
    int tidl = threadIdx.x;
    if (bid < NBX) {
        size_t idx = (size_t)bid * 256 + tidl;
        int k = (int)(idx % KIN);
        size_t row = idx / KIN;
        int t = (int)(row >> 8), b = (int)(row & 255);
        float v = 0.f;
        if (k < 128) v = x[((size_t)b * T_ + t) * D_ + k];
        else if (k < 256) v = mask[((size_t)b * T_ + t) * D_ + (k - 128)];
        else if (k == 256) v = ti[(size_t)b * T_ + t];
        g_xh[idx] = __float2half_rn(v);
    } else if (bid < NBX + NBW3) {
        size_t idx = (size_t)(bid - NBX) * 256 + tidl;
        g_w3[idx] = __float2half_rn(W_hh[idx]);
    } else if (bid < NBX + NBW3 + NBW) {
        size_t idx = (size_t)(bid - NBX - NBW3) * 256 + tidl;
        int k = (int)(idx % KIN); size_t g = idx / KIN;
        g_wih[idx] = (k < DIN) ? __float2half_rn(W_ih[g * DIN + k]) : __float2half_rn(0.0f);
    } else {
        size_t idx = (size_t)(bid - NBX - NBW3 - NBW) * 256 + tidl;
        if (idx < B_ * H_) { g_hf[0][idx] = 0.0f; g_hh[0][idx] = __float2half_rn(0.0f); }
        if (idx < 64) g_bars[idx] = 0u;
    }
}
__global__ void bar_zero() { if (threadIdx.x < 64) g_bars[threadIdx.x] = 0u; }

// ---------------- gi GEMM: W_ih-resident, x = n-slice, y = m-block (A L2 reuse) ----------------
__global__ __launch_bounds__(256, 2) void gi_gemm4(const float* __restrict__ b_ih,
                                                   const float* __restrict__ b_hh) {
    extern __shared__ char smc[];
    uint32_t sb = smem_u32(smc);
    uint32_t ast = sb + GI_WSM;
    const int tid = threadIdx.x, lane = tid & 31, wid = tid >> 5;
    const int wm = (wid >> 2) * 32;
    const int wn8 = (wid & 3) * 8;
    const int g4 = lane >> 2, tig = lane & 3;
    const int ni = blockIdx.x, n0 = ni * 32;
    const size_t mbase = (size_t)blockIdx.y * (M_REP * 64);

    // ---- load W_ih slice (5 chunks x 96 rows x 128B, swizzled) ----
    {
#pragma unroll 1
        for (int i = tid; i < 5 * 96 * 8; i += 256) {
            int chunk = i / 768, rem = i % 768;
            int rr = rem >> 3, c = rem & 7;
            int grow = (rr >> 5) * H_ + n0 + (rr & 31);
            uint32_t dst = sb + (uint32_t)(chunk * WCH + rr * 128 + ((c ^ (rr & 7)) << 4));
            cpa16(dst, g_wih + (size_t)grow * KIN + chunk * 64 + c * 8);
        }
        cpcommit(); cpwait0();
        __syncthreads();
    }

    const int arow0 = wm + (lane & 15);
    const int acsel = (lane >> 4);
    const int browA = ((lane < 16) ? 0 : 32) + wn8 + (lane & 7);
    const int browC = 64 + wn8 + (lane & 7);
    const int bcsel = (lane >> 3) & 1;

    const int gcol = n0 + wn8 + 2 * tig;
    float2 biasr = { b_ih[gcol] + b_hh[gcol], b_ih[gcol + 1] + b_hh[gcol + 1] };
    float2 biasz = { b_ih[H_ + gcol] + b_hh[H_ + gcol], b_ih[H_ + gcol + 1] + b_hh[H_ + gcol + 1] };
    float2 biasn = { b_ih[2 * H_ + gcol], b_ih[2 * H_ + gcol + 1] };

    auto issueA = [&](int s) {
        int rep = s / 5, chunk = s - rep * 5;
        uint32_t ab = ast + (uint32_t)((s & 3) * AST);
        const __half* Ag = g_xh + (mbase + (size_t)rep * 64) * KIN + chunk * 64;
#pragma unroll
        for (int i = 0; i < 2; i++) {
            int f = tid + 256 * i, r = f >> 3, c = f & 7;
            cpa16(ab + (uint32_t)(r * 128 + ((c ^ (r & 7)) << 4)),
                  Ag + (size_t)r * KIN + c * 8);
        }
        cpcommit();
    };

    float acc[2][3][4];
#pragma unroll
    for (int i = 0; i < 2; i++)
#pragma unroll
        for (int j = 0; j < 3; j++)
#pragma unroll
            for (int e = 0; e < 4; e++) acc[i][j][e] = 0.f;

    issueA(0); issueA(1); issueA(2);
#pragma unroll 1
    for (int s = 0; s < GI_NSTG; s++) {
        cpwait2();
        __syncthreads();
        int rep = s / 5, chunk = s - rep * 5;
        uint32_t ab = ast + (uint32_t)((s & 3) * AST);
        uint32_t wb = sb + (uint32_t)(chunk * WCH);
#pragma unroll
        for (int g = 0; g < 4; g++) {
            uint32_t A0[4], A1[4], B4[4], B2[2];
            {
                int c = 2 * g + acsel;
                int r0 = arow0, r1 = arow0 + 16;
                LDSM4(A0[0], A0[1], A0[2], A0[3], ab + (uint32_t)(r0 * 128 + ((c ^ (r0 & 7)) << 4)));
                LDSM4(A1[0], A1[1], A1[2], A1[3], ab + (uint32_t)(r1 * 128 + ((c ^ (r1 & 7)) << 4)));
            }
            {
                int c = 2 * g + bcsel;
                LDSM4(B4[0], B4[1], B4[2], B4[3], wb + (uint32_t)(browA * 128 + ((c ^ (browA & 7)) << 4)));
                LDSM2(B2[0], B2[1], wb + (uint32_t)(browC * 128 + ((c ^ (browC & 7)) << 4)));
            }
            mma_f16(acc[0][0], A0[0], A0[1], A0[2], A0[3], B4[0], B4[1]);
            mma_f16(acc[1][0], A1[0], A1[1], A1[2], A1[3], B4[0], B4[1]);
            mma_f16(acc[0][1], A0[0], A0[1], A0[2], A0[3], B4[2], B4[3]);
            mma_f16(acc[1][1], A1[0], A1[1], A1[2], A1[3], B4[2], B4[3]);
            mma_f16(acc[0][2], A0[0], A0[1], A0[2], A0[3], B2[0], B2[1]);
            mma_f16(acc[1][2], A1[0], A1[1], A1[2], A1[3], B2[0], B2[1]);
        }
        if (s + 3 < GI_NSTG) issueA(s + 3); else cpcommit();

        if (chunk == 4) {
            size_t rowbase = mbase + (size_t)rep * 64;
#pragma unroll
            for (int mt = 0; mt < 2; mt++)
#pragma unroll
                for (int rh = 0; rh < 2; rh++) {
                    size_t row = rowbase + wm + mt * 16 + g4 + 8 * rh;
                    __half* gp = g_gi + row * G_ + gcol;
                    *(__half2*)(gp)          = __floats2half2_rn(acc[mt][0][2 * rh] + biasr.x,
                                                                 acc[mt][0][2 * rh + 1] + biasr.y);
                    *(__half2*)(gp + H_)     = __floats2half2_rn(acc[mt][1][2 * rh] + biasz.x,
                                                                 acc[mt][1][2 * rh + 1] + biasz.y);
                    *(__half2*)(gp + 2 * H_) = __floats2half2_rn(acc[mt][2][2 * rh] + biasn.x,
                                                                 acc[mt][2][2 * rh + 1] + biasn.y);
                }
#pragma unroll
            for (int i = 0; i < 2; i++)
#pragma unroll
                for (int j = 0; j < 3; j++)
#pragma unroll
                    for (int e = 0; e < 4; e++) acc[i][j][e] = 0.f;
        }
    }
    cpwait0();
}

// ---------------- persistent GRU recurrence (CTA-granular barrier, fp16 gi) ----------------
__global__ __launch_bounds__(256, 1) void gru_persist() {
    extern __shared__ char smc[];
    uint32_t sb = smem_u32(smc);
    uint32_t ast = sb + W_SM;
    const int tid = threadIdx.x, lane = tid & 31, wid = tid >> 5;
    const int wm = (wid >> 2) * 32;
    const int wn8 = (wid & 3) * 8;
    const int g4 = lane >> 2, tig = lane & 3;
    const int mi = blockIdx.x >> 5, ni = blockIdx.x & 31;
    const int m0 = mi * 64, n0 = ni * 32;
    unsigned* barp = &g_bars[mi * 16];

    // ---- load W_hh slice once ----
    {
#pragma unroll 1
        for (int i = tid; i < 12288; i += 256) {
            int rr = i >> 7, cg = i & 127;
            int s = cg >> 3, c = cg & 7;
            int grow = (rr >> 5) * H_ + n0 + (rr & 31);
            uint32_t dst = sb + (uint32_t)(s * WCH + rr * 128 + ((c ^ (rr & 7)) << 4));
            cpa16(dst, g_w3 + (size_t)grow * H_ + s * 64 + c * 8);
        }
        cpcommit(); cpwait0();
        __syncthreads();
    }

    const int arow0 = wm + (lane & 15);
    const int acsel = (lane >> 4);
    const int browA = ((lane < 16) ? 0 : 32) + wn8 + (lane & 7);
    const int browC = 64 + wn8 + (lane & 7);
    const int bcsel = (lane >> 3) & 1;

    const int col2 = n0 + wn8 + 2 * tig;

    // register-carried h; h0 = 0
    float hc[8];
#pragma unroll
    for (int j = 0; j < 8; j++) hc[j] = 0.f;

    // gi prefetch for t=0 (fp16)
    float2 gir[4], giz[4], gin[4];
#pragma unroll
    for (int q = 0; q < 4; q++) {
        int row = m0 + wm + (q >> 1) * 16 + g4 + 8 * (q & 1);
        const __half* p = g_gi + (size_t)row * G_ + col2;
        gir[q] = __half22float2(*(const __half2*)(p));
        giz[q] = __half22float2(*(const __half2*)(p + H_));
        gin[q] = __half22float2(*(const __half2*)(p + 2 * H_));
    }

#pragma unroll 1
    for (int t = 0; t < T_; t++) {
        // ---- CTA-granular wait for h(t): 32 arrivals per prior step ----
        if (t > 0) {
            if (tid == 0) {
                unsigned v; const unsigned tgt = 32u * (unsigned)t;
                do { asm volatile("ld.acquire.gpu.global.u32 %0, [%1];" : "=r"(v) : "l"(barp)); } while (v < tgt);
            }
            __syncthreads();
        }

        const __half* __restrict__ Ah = g_hh[t & 1] + (size_t)m0 * H_;

        float acc[2][3][4];
#pragma unroll
        for (int i = 0; i < 2; i++)
#pragma unroll
            for (int j = 0; j < 3; j++)
#pragma unroll
                for (int e = 0; e < 4; e++) acc[i][j][e] = 0.f;

        auto issueA = [&](int s) {
            int buf = s & 3;
            uint32_t ab = ast + (uint32_t)(buf * AST);
            int kc = s * 64;
#pragma unroll
            for (int i = 0; i < 2; i++) {
                int f = tid + 256 * i, r = f >> 3, c = f & 7;
                cpa16(ab + (uint32_t)(r * 128 + ((c ^ (r & 7)) << 4)),
                      Ah + (size_t)r * H_ + kc + c * 8);
            }
            cpcommit();
        };
        issueA(0); issueA(1); issueA(2);
#pragma unroll 1
        for (int s = 0; s < 16; s++) {
            cpwait2();
            __syncthreads();
            uint32_t ab = ast + (uint32_t)((s & 3) * AST);
            uint32_t wb = sb + (uint32_t)(s * WCH);
#pragma unroll
            for (int g = 0; g < 4; g++) {
                uint32_t A0[4], A1[4], B4[4], B2[2];
                {
                    int c = 2 * g + acsel;
                    int r0 = arow0, r1 = arow0 + 16;
                    LDSM4(A0[0], A0[1], A0[2], A0[3], ab + (uint32_t)(r0 * 128 + ((c ^ (r0 & 7)) << 4)));
                    LDSM4(A1[0], A1[1], A1[2], A1[3], ab + (uint32_t)(r1 * 128 + ((c ^ (r1 & 7)) << 4)));
                }
                {
                    int c = 2 * g + bcsel;
                    LDSM4(B4[0], B4[1], B4[2], B4[3], wb + (uint32_t)(browA * 128 + ((c ^ (browA & 7)) << 4)));
                    LDSM2(B2[0], B2[1], wb + (uint32_t)(browC * 128 + ((c ^ (browC & 7)) << 4)));
                }
                mma_f16(acc[0][0], A0[0], A0[1], A0[2], A0[3], B4[0], B4[1]);
                mma_f16(acc[1][0], A1[0], A1[1], A1[2], A1[3], B4[0], B4[1]);
                mma_f16(acc[0][1], A0[0], A0[1], A0[2], A0[3], B4[2], B4[3]);
                mma_f16(acc[1][1], A1[0], A1[1], A1[2], A1[3], B4[2], B4[3]);
                mma_f16(acc[0][2], A0[0], A0[1], A0[2], A0[3], B2[0], B2[1]);
                mma_f16(acc[1][2], A1[0], A1[1], A1[2], A1[3], B2[0], B2[1]);
            }
            if (s + 3 < 16) issueA(s + 3); else cpcommit();
        }
        cpwait0();

        // ---- register-resident gate epilogue (biases folded into gi at pack) ----
        {
            __half* __restrict__ hxB = g_hh[(t + 1) & 1];
#pragma unroll
            for (int q = 0; q < 4; q++) {
                int mt = q >> 1, rh = q & 1;
                int row = m0 + wm + mt * 16 + g4 + 8 * rh;
                float o0, o1;
                {
                    float rr = fsig(gir[q].x + acc[mt][0][2 * rh]);
                    float zz = fsig(giz[q].x + acc[mt][1][2 * rh]);
                    float nn = ftanh_(gin[q].x + rr * acc[mt][2][2 * rh]);
                    o0 = (1.0f - zz) * nn + zz * hc[2 * q];
                }
                {
                    float rr = fsig(gir[q].y + acc[mt][0][2 * rh + 1]);
                    float zz = fsig(giz[q].y + acc[mt][1][2 * rh + 1]);
                    float nn = ftanh_(gin[q].y + rr * acc[mt][2][2 * rh + 1]);
                    o1 = (1.0f - zz) * nn + zz * hc[2 * q + 1];
                }
                hc[2 * q] = o0; hc[2 * q + 1] = o1;
                *(__half2*)(hxB + (size_t)row * H_ + col2) = __floats2half2_rn(o0, o1);
                if (t == T_ - 1) {
                    float2 ov = { o0, o1 };
                    *(float2*)(g_hf[0] + (size_t)row * H_ + col2) = ov;
                }
            }
        }

        // ---- publish h(t+1) (CTA-granular), then prefetch gi(t+1) ----
        __syncthreads();
        if (tid == 0)
            asm volatile("red.release.gpu.global.add.u32 [%0], 1;" :: "l"(barp) : "memory");

        if (t + 1 < T_) {
            const __half* __restrict__ gi_t = g_gi + (size_t)(t + 1) * B_ * G_;
#pragma unroll
            for (int q = 0; q < 4; q++) {
                int row = m0 + wm + (q >> 1) * 16 + g4 + 8 * (q & 1);
                const __half* p = gi_t + (size_t)row * G_ + col2;
                gir[q] = __half22float2(*(const __half2*)(p));
                giz[q] = __half22float2(*(const __half2*)(p + H_));
                gin[q] = __half22float2(*(const __half2*)(p + 2 * H_));
            }
        }
    }
}

// ---------------- output head ----------------
__global__ void out_gemm(const float* __restrict__ Wout, const float* __restrict__ bout, float* __restrict__ out) {
    const int b = blockIdx.x;
    const int wid = threadIdx.x >> 5, lane = threadIdx.x & 31;
    const int o0 = blockIdx.y * 32 + wid * 4;
    const float* __restrict__ h = g_hf[0] + (size_t)b * H_;
    float acc[4] = {0.f, 0.f, 0.f, 0.f};
#pragma unroll
    for (int kk = 0; kk < 8; kk++) {
        int k = kk * 128 + lane * 4;
        float4 hv = *(const float4*)(h + k);
#pragma unroll
        for (int j = 0; j < 4; j++) {
            float4 w = *(const float4*)(Wout + (size_t)(o0 + j) * H_ + k);
            acc[j] += hv.x * w.x + hv.y * w.y + hv.z * w.z + hv.w * w.w;
        }
    }
#pragma unroll
    for (int j = 0; j < 4; j++) {
        float v = acc[j];
#pragma unroll
        for (int s = 16; s > 0; s >>= 1) v += __shfl_xor_sync(0xffffffffu, v, s);
        if (lane == 0) out[(size_t)b * O_ + o0 + j] = v + bout[o0 + j];
    }
}

// ---------------- launch ----------------
extern "C" void kernel_launch(void* const* d_in, const int* in_sizes, int n_in,
                              void* d_out, int out_size) {
    const float* x     = (const float*)d_in[0];
    const float* mask  = (const float*)d_in[1];
    const float* ti    = (const float*)d_in[2];
    const float* W_ih  = (const float*)d_in[3];
    const float* W_hh  = (const float*)d_in[4];
    const float* b_ih  = (const float*)d_in[5];
    const float* b_hh  = (const float*)d_in[6];
    const float* W_out = (const float*)d_in[7];
    const float* b_out = (const float*)d_in[8];
    float* out = (float*)d_out;

    static int smem_set = 0;
    if (!smem_set) {
        cudaFuncSetAttribute(gi_gemm4, cudaFuncAttributeMaxDynamicSharedMemorySize, GI_SMEM2);
        cudaFuncSetAttribute(gru_persist, cudaFuncAttributeMaxDynamicSharedMemorySize, P_SMEM);
        smem_set = 1;
    }

    pack_fused<<<NBX + NBW3 + NBW + NBZ, 256>>>(x, mask, ti, W_ih, W_hh);         // 0
    gi_gemm4<<<dim3(32, (T_ * B_) / (M_REP * 64)), 256, GI_SMEM2>>>(b_ih, b_hh);  // 1
    bar_zero<<<1, 64>>>();                                                         // 2
    gru_persist<<<128, 256, P_SMEM>>>();                                           // 3 (profiled)
    out_gemm<<<dim3(B_, O_ / 32), 256>>>(W_out, b_out, out);                       // 4
}

// round 16
// speedup vs baseline: 1.1345x; 1.0619x over previous
#include <cuda_runtime.h>
#include <cuda_fp16.h>
#include <cstdint>
#include <math.h>

#define B_   256
#define T_   512
#define D_   128
#define H_   1024
#define G_   3072
#define O_   128
#define DIN  257
#define KIN  320

// ---- persistent kernel smem ----
#define WCH     12288                  // one k-chunk of W: 96 rows x 128B
#define W_SM    (16 * WCH)             // 196608
#define AST2    4096                   // per-warpgroup A stage: 32 rows x 128B
#define P_SMEM  (W_SM + 2 * 4 * AST2)  // 229376

// ---- gi kernel smem ----
#define AST     8192
#define GI_WSM   (5 * WCH)             // 61440
#define GI_SMEM2 (GI_WSM + 4 * AST)    // 94208 -> 2 CTAs/SM
#define M_REP    8
#define GI_NSTG  (M_REP * 5)

// ---------------- scratch ----------------
__device__ __half g_gi[(size_t)T_ * B_ * G_];     // fp16 gi (+ folded biases)
__device__ __half g_xh[(size_t)(T_ * B_) * KIN];
__device__ __half g_wih[(size_t)G_ * KIN];
__device__ __half g_w3[(size_t)G_ * H_];
__device__ float  g_hf[2][B_ * H_];
__device__ __half g_hh[2][B_ * H_];
__device__ unsigned g_bars[64];

// ---------------- helpers ----------------
__device__ __forceinline__ float fsig(float x) {
    float e; asm("ex2.approx.f32 %0, %1;" : "=f"(e) : "f"(-1.4426950408889634f * x));
    float r; asm("rcp.approx.f32 %0, %1;" : "=f"(r) : "f"(1.0f + e));
    return r;
}
__device__ __forceinline__ float ftanh_(float x) {
    float e; asm("ex2.approx.f32 %0, %1;" : "=f"(e) : "f"(-2.8853900817779268f * x));
    float r; asm("rcp.approx.f32 %0, %1;" : "=f"(r) : "f"(1.0f + e));
    return 2.0f * r - 1.0f;
}
__device__ __forceinline__ uint32_t smem_u32(const void* p) {
    uint32_t a; asm("{ .reg .u64 t; cvta.to.shared.u64 t, %1; cvt.u32.u64 %0, t; }" : "=r"(a) : "l"(p)); return a;
}
__device__ __forceinline__ void cpa16(uint32_t d, const void* s) {
    asm volatile("cp.async.cg.shared.global [%0], [%1], 16;" :: "r"(d), "l"(s));
}
__device__ __forceinline__ void cpcommit() { asm volatile("cp.async.commit_group;"); }
__device__ __forceinline__ void cpwait2()  { asm volatile("cp.async.wait_group 2;" ::: "memory"); }
__device__ __forceinline__ void cpwait0()  { asm volatile("cp.async.wait_group 0;" ::: "memory"); }
#define WGBAR(id) asm volatile("bar.sync %0, 128;" :: "r"(id) : "memory")

#define LDSM4(r0, r1, r2, r3, addr) \
    asm volatile("ldmatrix.sync.aligned.m8n8.x4.shared.b16 {%0,%1,%2,%3}, [%4];" \
        : "=r"(r0), "=r"(r1), "=r"(r2), "=r"(r3) : "r"(addr))
#define LDSM2(r0, r1, addr) \
    asm volatile("ldmatrix.sync.aligned.m8n8.x2.shared.b16 {%0,%1}, [%2];" \
        : "=r"(r0), "=r"(r1) : "r"(addr))

__device__ __forceinline__ void mma_f16(float* d, uint32_t a0, uint32_t a1, uint32_t a2, uint32_t a3,
                                        uint32_t b0, uint32_t b1) {
    asm volatile("mma.sync.aligned.m16n8k16.row.col.f32.f16.f16.f32 "
        "{%0,%1,%2,%3},{%4,%5,%6,%7},{%8,%9},{%0,%1,%2,%3};\n"
        : "+f"(d[0]), "+f"(d[1]), "+f"(d[2]), "+f"(d[3])
        : "r"(a0), "r"(a1), "r"(a2), "r"(a3), "r"(b0), "r"(b1));
}

// ---------------- fused pack kernel ----------------
#define NBX  163840
#define NBW3 12288
#define NBW  3840
#define NBZ  1024
__global__ void pack_fused(const float* __restrict__ x, const float* __restrict__ mask,
                           const float* __restrict__ ti, const float* __restrict__ W_ih,
                           const float* __restrict__ W_hh) {
    long long bid = blockIdx.x;
    int tidl = threadIdx.x;
    if (bid < NBX) {
        size_t idx = (size_t)bid * 256 + tidl;
        int k = (int)(idx % KIN);
        size_t row = idx / KIN;
        int t = (int)(row >> 8), b = (int)(row & 255);
        float v = 0.f;
        if (k < 128) v = x[((size_t)b * T_ + t) * D_ + k];
        else if (k < 256) v = mask[((size_t)b * T_ + t) * D_ + (k - 128)];
        else if (k == 256) v = ti[(size_t)b * T_ + t];
        g_xh[idx] = __float2half_rn(v);
    } else if (bid < NBX + NBW3) {
        size_t idx = (size_t)(bid - NBX) * 256 + tidl;
        g_w3[idx] = __float2half_rn(W_hh[idx]);
    } else if (bid < NBX + NBW3 + NBW) {
        size_t idx = (size_t)(bid - NBX - NBW3) * 256 + tidl;
        int k = (int)(idx % KIN); size_t g = idx / KIN;
        g_wih[idx] = (k < DIN) ? __float2half_rn(W_ih[g * DIN + k]) : __float2half_rn(0.0f);
    } else {
        size_t idx = (size_t)(bid - NBX - NBW3 - NBW) * 256 + tidl;
        if (idx < B_ * H_) { g_hf[0][idx] = 0.0f; g_hh[0][idx] = __float2half_rn(0.0f); }
        if (idx < 64) g_bars[idx] = 0u;
    }
}
__global__ void bar_zero() { if (threadIdx.x < 64) g_bars[threadIdx.x] = 0u; }

// ---------------- gi GEMM: W_ih-resident, x = n-slice, y = m-block (A L2 reuse) ----------------
__global__ __launch_bounds__(256, 2) void gi_gemm4(const float* __restrict__ b_ih,
                                                   const float* __restrict__ b_hh) {
    extern __shared__ char smc[];
    uint32_t sb = smem_u32(smc);
    uint32_t ast = sb + GI_WSM;
    const int tid = threadIdx.x, lane = tid & 31, wid = tid >> 5;
    const int wm = (wid >> 2) * 32;
    const int wn8 = (wid & 3) * 8;
    const int g4 = lane >> 2, tig = lane & 3;
    const int ni = blockIdx.x, n0 = ni * 32;
    const size_t mbase = (size_t)blockIdx.y * (M_REP * 64);

    {
#pragma unroll 1
        for (int i = tid; i < 5 * 96 * 8; i += 256) {
            int chunk = i / 768, rem = i % 768;
            int rr = rem >> 3, c = rem & 7;
            int grow = (rr >> 5) * H_ + n0 + (rr & 31);
            uint32_t dst = sb + (uint32_t)(chunk * WCH + rr * 128 + ((c ^ (rr & 7)) << 4));
            cpa16(dst, g_wih + (size_t)grow * KIN + chunk * 64 + c * 8);
        }
        cpcommit(); cpwait0();
        __syncthreads();
    }

    const int arow0 = wm + (lane & 15);
    const int acsel = (lane >> 4);
    const int browA = ((lane < 16) ? 0 : 32) + wn8 + (lane & 7);
    const int browC = 64 + wn8 + (lane & 7);
    const int bcsel = (lane >> 3) & 1;

    const int gcol = n0 + wn8 + 2 * tig;
    float2 biasr = { b_ih[gcol] + b_hh[gcol], b_ih[gcol + 1] + b_hh[gcol + 1] };
    float2 biasz = { b_ih[H_ + gcol] + b_hh[H_ + gcol], b_ih[H_ + gcol + 1] + b_hh[H_ + gcol + 1] };
    float2 biasn = { b_ih[2 * H_ + gcol], b_ih[2 * H_ + gcol + 1] };

    auto issueA = [&](int s) {
        int rep = s / 5, chunk = s - rep * 5;
        uint32_t ab = ast + (uint32_t)((s & 3) * AST);
        const __half* Ag = g_xh + (mbase + (size_t)rep * 64) * KIN + chunk * 64;
#pragma unroll
        for (int i = 0; i < 2; i++) {
            int f = tid + 256 * i, r = f >> 3, c = f & 7;
            cpa16(ab + (uint32_t)(r * 128 + ((c ^ (r & 7)) << 4)),
                  Ag + (size_t)r * KIN + c * 8);
        }
        cpcommit();
    };

    float acc[2][3][4];
#pragma unroll
    for (int i = 0; i < 2; i++)
#pragma unroll
        for (int j = 0; j < 3; j++)
#pragma unroll
            for (int e = 0; e < 4; e++) acc[i][j][e] = 0.f;

    issueA(0); issueA(1); issueA(2);
#pragma unroll 1
    for (int s = 0; s < GI_NSTG; s++) {
        cpwait2();
        __syncthreads();
        int rep = s / 5, chunk = s - rep * 5;
        uint32_t ab = ast + (uint32_t)((s & 3) * AST);
        uint32_t wb = sb + (uint32_t)(chunk * WCH);
#pragma unroll
        for (int g = 0; g < 4; g++) {
            uint32_t A0[4], A1[4], B4[4], B2[2];
            {
                int c = 2 * g + acsel;
                int r0 = arow0, r1 = arow0 + 16;
                LDSM4(A0[0], A0[1], A0[2], A0[3], ab + (uint32_t)(r0 * 128 + ((c ^ (r0 & 7)) << 4)));
                LDSM4(A1[0], A1[1], A1[2], A1[3], ab + (uint32_t)(r1 * 128 + ((c ^ (r1 & 7)) << 4)));
            }
            {
                int c = 2 * g + bcsel;
                LDSM4(B4[0], B4[1], B4[2], B4[3], wb + (uint32_t)(browA * 128 + ((c ^ (browA & 7)) << 4)));
                LDSM2(B2[0], B2[1], wb + (uint32_t)(browC * 128 + ((c ^ (browC & 7)) << 4)));
            }
            mma_f16(acc[0][0], A0[0], A0[1], A0[2], A0[3], B4[0], B4[1]);
            mma_f16(acc[1][0], A1[0], A1[1], A1[2], A1[3], B4[0], B4[1]);
            mma_f16(acc[0][1], A0[0], A0[1], A0[2], A0[3], B4[2], B4[3]);
            mma_f16(acc[1][1], A1[0], A1[1], A1[2], A1[3], B4[2], B4[3]);
            mma_f16(acc[0][2], A0[0], A0[1], A0[2], A0[3], B2[0], B2[1]);
            mma_f16(acc[1][2], A1[0], A1[1], A1[2], A1[3], B2[0], B2[1]);
        }
        if (s + 3 < GI_NSTG) issueA(s + 3); else cpcommit();

        if (chunk == 4) {
            size_t rowbase = mbase + (size_t)rep * 64;
#pragma unroll
            for (int mt = 0; mt < 2; mt++)
#pragma unroll
                for (int rh = 0; rh < 2; rh++) {
                    size_t row = rowbase + wm + mt * 16 + g4 + 8 * rh;
                    __half* gp = g_gi + row * G_ + gcol;
                    *(__half2*)(gp)          = __floats2half2_rn(acc[mt][0][2 * rh] + biasr.x,
                                                                 acc[mt][0][2 * rh + 1] + biasr.y);
                    *(__half2*)(gp + H_)     = __floats2half2_rn(acc[mt][1][2 * rh] + biasz.x,
                                                                 acc[mt][1][2 * rh + 1] + biasz.y);
                    *(__half2*)(gp + 2 * H_) = __floats2half2_rn(acc[mt][2][2 * rh] + biasn.x,
                                                                 acc[mt][2][2 * rh + 1] + biasn.y);
                }
#pragma unroll
            for (int i = 0; i < 2; i++)
#pragma unroll
                for (int j = 0; j < 3; j++)
#pragma unroll
                    for (int e = 0; e < 4; e++) acc[i][j][e] = 0.f;
        }
    }
    cpwait0();
}

// ---------------- persistent GRU recurrence (two independent warp-group pipelines) ----------------
// wg0 = warps 0-3 (m-rows 0-31), wg1 = warps 4-7 (m-rows 32-63). Each wg: own 4-stage
// A buffer, own named barrier, own global-barrier arrival. 64 arrivals/group/step.
__global__ __launch_bounds__(256, 1) void gru_persist() {
    extern __shared__ char smc[];
    uint32_t sb = smem_u32(smc);
    const int tid = threadIdx.x, lane = tid & 31, wid = tid >> 5;
    const int wg = tid >> 7;                    // warp-group 0/1
    const int wn8 = (wid & 3) * 8;
    const int g4 = lane >> 2, tig = lane & 3;
    const int mi = blockIdx.x >> 5, ni = blockIdx.x & 31;
    const int m0 = blockIdx.x >> 5 ? (blockIdx.x >> 5) * 64 : 0;
    const int m0_ = mi * 64, n0 = ni * 32;
    (void)m0;
    uint32_t ast = sb + W_SM + (uint32_t)wg * (4 * AST2);
    unsigned* barp = &g_bars[mi * 16];
    const int bar_id = wg + 1;

    // ---- load W_hh slice once (CTA-wide) ----
    {
#pragma unroll 1
        for (int i = tid; i < 12288; i += 256) {
            int rr = i >> 7, cg = i & 127;
            int s = cg >> 3, c = cg & 7;
            int grow = (rr >> 5) * H_ + n0 + (rr & 31);
            uint32_t dst = sb + (uint32_t)(s * WCH + rr * 128 + ((c ^ (rr & 7)) << 4));
            cpa16(dst, g_w3 + (size_t)grow * H_ + s * 64 + c * 8);
        }
        cpcommit(); cpwait0();
        __syncthreads();
    }

    const int ltid = tid & 127;
    const int arow0 = lane & 15;               // within 32-row wg stage buffer
    const int acsel = (lane >> 4);
    const int browA = ((lane < 16) ? 0 : 32) + wn8 + (lane & 7);
    const int browC = 64 + wn8 + (lane & 7);
    const int bcsel = (lane >> 3) & 1;

    const int col2 = n0 + wn8 + 2 * tig;
    const int mrow0 = m0_ + wg * 32;           // this wg's first m-row

    // register-carried h; h0 = 0
    float hc[8];
#pragma unroll
    for (int j = 0; j < 8; j++) hc[j] = 0.f;

    // gi prefetch for t=0 (fp16)
    float2 gir[4], giz[4], gin[4];
#pragma unroll
    for (int q = 0; q < 4; q++) {
        int row = mrow0 + (q >> 1) * 16 + g4 + 8 * (q & 1);
        const __half* p = g_gi + (size_t)row * G_ + col2;
        gir[q] = __half22float2(*(const __half2*)(p));
        giz[q] = __half22float2(*(const __half2*)(p + H_));
        gin[q] = __half22float2(*(const __half2*)(p + 2 * H_));
    }

#pragma unroll 1
    for (int t = 0; t < T_; t++) {
        // ---- wg-granular wait for h(t): 64 arrivals per prior step ----
        if (t > 0) {
            if (ltid == 0) {
                unsigned v; const unsigned tgt = 64u * (unsigned)t;
                do { asm volatile("ld.acquire.gpu.global.u32 %0, [%1];" : "=r"(v) : "l"(barp)); } while (v < tgt);
            }
            WGBAR(bar_id);
        }

        const __half* __restrict__ Ah = g_hh[t & 1] + (size_t)mrow0 * H_;

        float acc[2][3][4];
#pragma unroll
        for (int i = 0; i < 2; i++)
#pragma unroll
            for (int j = 0; j < 3; j++)
#pragma unroll
                for (int e = 0; e < 4; e++) acc[i][j][e] = 0.f;

        // wg A pipeline: 32 rows x 64 halves per stage = 256 x 16B, 128 threads x 2
        auto issueA = [&](int s) {
            uint32_t ab = ast + (uint32_t)((s & 3) * AST2);
            int kc = s * 64;
#pragma unroll
            for (int i = 0; i < 2; i++) {
                int f = ltid + 128 * i, r = f >> 3, c = f & 7;
                cpa16(ab + (uint32_t)(r * 128 + ((c ^ (r & 7)) << 4)),
                      Ah + (size_t)r * H_ + kc + c * 8);
            }
            cpcommit();
        };
        issueA(0); issueA(1); issueA(2);
#pragma unroll 1
        for (int s = 0; s < 16; s++) {
            cpwait2();
            WGBAR(bar_id);
            uint32_t ab = ast + (uint32_t)((s & 3) * AST2);
            uint32_t wb = sb + (uint32_t)(s * WCH);
#pragma unroll
            for (int g = 0; g < 4; g++) {
                uint32_t A0[4], A1[4], B4[4], B2[2];
                {
                    int c = 2 * g + acsel;
                    int r0 = arow0, r1 = arow0 + 16;
                    LDSM4(A0[0], A0[1], A0[2], A0[3], ab + (uint32_t)(r0 * 128 + ((c ^ (r0 & 7)) << 4)));
                    LDSM4(A1[0], A1[1], A1[2], A1[3], ab + (uint32_t)(r1 * 128 + ((c ^ (r1 & 7)) << 4)));
                }
                {
                    int c = 2 * g + bcsel;
                    LDSM4(B4[0], B4[1], B4[2], B4[3], wb + (uint32_t)(browA * 128 + ((c ^ (browA & 7)) << 4)));
                    LDSM2(B2[0], B2[1], wb + (uint32_t)(browC * 128 + ((c ^ (browC & 7)) << 4)));
                }
                mma_f16(acc[0][0], A0[0], A0[1], A0[2], A0[3], B4[0], B4[1]);
                mma_f16(acc[1][0], A1[0], A1[1], A1[2], A1[3], B4[0], B4[1]);
                mma_f16(acc[0][1], A0[0], A0[1], A0[2], A0[3], B4[2], B4[3]);
                mma_f16(acc[1][1], A1[0], A1[1], A1[2], A1[3], B4[2], B4[3]);
                mma_f16(acc[0][2], A0[0], A0[1], A0[2], A0[3], B2[0], B2[1]);
                mma_f16(acc[1][2], A1[0], A1[1], A1[2], A1[3], B2[0], B2[1]);
            }
            if (s + 3 < 16) issueA(s + 3); else cpcommit();
        }
        cpwait0();

        // ---- register-resident gate epilogue ----
        {
            __half* __restrict__ hxB = g_hh[(t + 1) & 1];
#pragma unroll
            for (int q = 0; q < 4; q++) {
                int mt = q >> 1, rh = q & 1;
                int row = mrow0 + mt * 16 + g4 + 8 * rh;
                float o0, o1;
                {
                    float rr = fsig(gir[q].x + acc[mt][0][2 * rh]);
                    float zz = fsig(giz[q].x + acc[mt][1][2 * rh]);
                    float nn = ftanh_(gin[q].x + rr * acc[mt][2][2 * rh]);
                    o0 = (1.0f - zz) * nn + zz * hc[2 * q];
                }
                {
                    float rr = fsig(gir[q].y + acc[mt][0][2 * rh + 1]);
                    float zz = fsig(giz[q].y + acc[mt][1][2 * rh + 1]);
                    float nn = ftanh_(gin[q].y + rr * acc[mt][2][2 * rh + 1]);
                    o1 = (1.0f - zz) * nn + zz * hc[2 * q + 1];
                }
                hc[2 * q] = o0; hc[2 * q + 1] = o1;
                *(__half2*)(hxB + (size_t)row * H_ + col2) = __floats2half2_rn(o0, o1);
                if (t == T_ - 1) {
                    float2 ov = { o0, o1 };
                    *(float2*)(g_hf[0] + (size_t)row * H_ + col2) = ov;
                }
            }
        }

        // ---- publish h(t+1) (wg-granular), then prefetch gi(t+1) ----
        WGBAR(bar_id);
        if (ltid == 0)
            asm volatile("red.release.gpu.global.add.u32 [%0], 1;" :: "l"(barp) : "memory");

        if (t + 1 < T_) {
            const __half* __restrict__ gi_t = g_gi + (size_t)(t + 1) * B_ * G_;
#pragma unroll
            for (int q = 0; q < 4; q++) {
                int row = mrow0 + (q >> 1) * 16 + g4 + 8 * (q & 1);
                const __half* p = gi_t + (size_t)row * G_ + col2;
                gir[q] = __half22float2(*(const __half2*)(p));
                giz[q] = __half22float2(*(const __half2*)(p + H_));
                gin[q] = __half22float2(*(const __half2*)(p + 2 * H_));
            }
        }
    }
}

// ---------------- output head ----------------
__global__ void out_gemm(const float* __restrict__ Wout, const float* __restrict__ bout, float* __restrict__ out) {
    const int b = blockIdx.x;
    const int wid = threadIdx.x >> 5, lane = threadIdx.x & 31;
    const int o0 = blockIdx.y * 32 + wid * 4;
    const float* __restrict__ h = g_hf[0] + (size_t)b * H_;
    float acc[4] = {0.f, 0.f, 0.f, 0.f};
#pragma unroll
    for (int kk = 0; kk < 8; kk++) {
        int k = kk * 128 + lane * 4;
        float4 hv = *(const float4*)(h + k);
#pragma unroll
        for (int j = 0; j < 4; j++) {
            float4 w = *(const float4*)(Wout + (size_t)(o0 + j) * H_ + k);
            acc[j] += hv.x * w.x + hv.y * w.y + hv.z * w.z + hv.w * w.w;
        }
    }
#pragma unroll
    for (int j = 0; j < 4; j++) {
        float v = acc[j];
#pragma unroll
        for (int s = 16; s > 0; s >>= 1) v += __shfl_xor_sync(0xffffffffu, v, s);
        if (lane == 0) out[(size_t)b * O_ + o0 + j] = v + bout[o0 + j];
    }
}

// ---------------- launch ----------------
extern "C" void kernel_launch(void* const* d_in, const int* in_sizes, int n_in,
                              void* d_out, int out_size) {
    const float* x     = (const float*)d_in[0];
    const float* mask  = (const float*)d_in[1];
    const float* ti    = (const float*)d_in[2];
    const float* W_ih  = (const float*)d_in[3];
    const float* W_hh  = (const float*)d_in[4];
    const float* b_ih  = (const float*)d_in[5];
    const float* b_hh  = (const float*)d_in[6];
    const float* W_out = (const float*)d_in[7];
    const float* b_out = (const float*)d_in[8];
    float* out = (float*)d_out;

    static int smem_set = 0;
    if (!smem_set) {
        cudaFuncSetAttribute(gi_gemm4, cudaFuncAttributeMaxDynamicSharedMemorySize, GI_SMEM2);
        cudaFuncSetAttribute(gru_persist, cudaFuncAttributeMaxDynamicSharedMemorySize, P_SMEM);
        smem_set = 1;
    }

    pack_fused<<<NBX + NBW3 + NBW + NBZ, 256>>>(x, mask, ti, W_ih, W_hh);         // 0
    gi_gemm4<<<dim3(32, (T_ * B_) / (M_REP * 64)), 256, GI_SMEM2>>>(b_ih, b_hh);  // 1
    bar_zero<<<1, 64>>>();                                                         // 2
    gru_persist<<<128, 256, P_SMEM>>>();                                           // 3 (profiled)
    out_gemm<<<dim3(B_, O_ / 32), 256>>>(W_out, b_out, out);                       // 4
}

// round 17
// speedup vs baseline: 1.2396x; 1.0927x over previous
#include <cuda_runtime.h>
#include <cuda_fp16.h>
#include <cstdint>
#include <math.h>

#define B_   256
#define T_   512
#define D_   128
#define H_   1024
#define G_   3072
#define O_   128
#define DIN  257
#define KIN  320

// ---- persistent kernel smem ----
#define WCH     12288                  // one 64-col k-chunk of W: 96 rows x 128B
#define W_SM    (16 * WCH)             // 196608
#define ASTP    8192                   // per-wg BK=128 A stage: 2 sub-chunks x 32 rows x 128B
#define P_SMEM  (W_SM + 2 * 2 * ASTP)  // 229376

// ---- gi kernel smem ----
#define AST     8192
#define GI_WSM   (5 * WCH)             // 61440
#define GI_SMEM2 (GI_WSM + 4 * AST)    // 94208 -> 2 CTAs/SM
#define M_REP    8
#define GI_NSTG  (M_REP * 5)

// ---------------- scratch ----------------
__device__ __half g_gi[(size_t)T_ * B_ * G_];     // fp16 gi (+ folded biases)
__device__ __half g_xh[(size_t)(T_ * B_) * KIN];
__device__ __half g_wih[(size_t)G_ * KIN];
__device__ __half g_w3[(size_t)G_ * H_];
__device__ float  g_hf[2][B_ * H_];
__device__ __half g_hh[2][B_ * H_];
__device__ unsigned g_bars[64];

// ---------------- helpers ----------------
__device__ __forceinline__ float fsig(float x) {
    float e; asm("ex2.approx.f32 %0, %1;" : "=f"(e) : "f"(-1.4426950408889634f * x));
    float r; asm("rcp.approx.f32 %0, %1;" : "=f"(r) : "f"(1.0f + e));
    return r;
}
__device__ __forceinline__ float ftanh_(float x) {
    float e; asm("ex2.approx.f32 %0, %1;" : "=f"(e) : "f"(-2.8853900817779268f * x));
    float r; asm("rcp.approx.f32 %0, %1;" : "=f"(r) : "f"(1.0f + e));
    return 2.0f * r - 1.0f;
}
__device__ __forceinline__ uint32_t smem_u32(const void* p) {
    uint32_t a; asm("{ .reg .u64 t; cvta.to.shared.u64 t, %1; cvt.u32.u64 %0, t; }" : "=r"(a) : "l"(p)); return a;
}
__device__ __forceinline__ void cpa16(uint32_t d, const void* s) {
    asm volatile("cp.async.cg.shared.global [%0], [%1], 16;" :: "r"(d), "l"(s));
}
__device__ __forceinline__ void cpcommit() { asm volatile("cp.async.commit_group;"); }
__device__ __forceinline__ void cpwait2()  { asm volatile("cp.async.wait_group 2;" ::: "memory"); }
__device__ __forceinline__ void cpwait0()  { asm volatile("cp.async.wait_group 0;" ::: "memory"); }
#define WGBAR(id) asm volatile("bar.sync %0, 128;" :: "r"(id) : "memory")

#define LDSM4(r0, r1, r2, r3, addr) \
    asm volatile("ldmatrix.sync.aligned.m8n8.x4.shared.b16 {%0,%1,%2,%3}, [%4];" \
        : "=r"(r0), "=r"(r1), "=r"(r2), "=r"(r3) : "r"(addr))
#define LDSM2(r0, r1, addr) \
    asm volatile("ldmatrix.sync.aligned.m8n8.x2.shared.b16 {%0,%1}, [%2];" \
        : "=r"(r0), "=r"(r1) : "r"(addr))

__device__ __forceinline__ void mma_f16(float* d, uint32_t a0, uint32_t a1, uint32_t a2, uint32_t a3,
                                        uint32_t b0, uint32_t b1) {
    asm volatile("mma.sync.aligned.m16n8k16.row.col.f32.f16.f16.f32 "
        "{%0,%1,%2,%3},{%4,%5,%6,%7},{%8,%9},{%0,%1,%2,%3};\n"
        : "+f"(d[0]), "+f"(d[1]), "+f"(d[2]), "+f"(d[3])
        : "r"(a0), "r"(a1), "r"(a2), "r"(a3), "r"(b0), "r"(b1));
}

// ---------------- vectorized pack kernel (8 elems/thread) ----------------
#define PBX  20480    // 131072 rows x 40 k8 / 256
#define PBW3 1536     // 3145728 / 8 / 256
#define PBW  480      // 3072 x 40 / 256
#define PBZ  128      // 262144 / 8 / 256
__global__ void pack_fused(const float* __restrict__ x, const float* __restrict__ mask,
                           const float* __restrict__ ti, const float* __restrict__ W_ih,
                           const float* __restrict__ W_hh) {
    int bid = blockIdx.x;
    int tid = threadIdx.x;
    if (bid < PBX) {
        int idx = bid * 256 + tid;
        int k8 = idx % 40;
        int row = idx / 40;
        int t = row >> 8, b = row & 255;
        int k0 = k8 * 8;
        float v[8] = {0.f, 0.f, 0.f, 0.f, 0.f, 0.f, 0.f, 0.f};
        if (k0 < 128) {
            const float* p = x + ((size_t)b * T_ + t) * D_ + k0;
            float4 a = *(const float4*)p, c = *(const float4*)(p + 4);
            v[0]=a.x; v[1]=a.y; v[2]=a.z; v[3]=a.w; v[4]=c.x; v[5]=c.y; v[6]=c.z; v[7]=c.w;
        } else if (k0 < 256) {
            const float* p = mask + ((size_t)b * T_ + t) * D_ + (k0 - 128);
            float4 a = *(const float4*)p, c = *(const float4*)(p + 4);
            v[0]=a.x; v[1]=a.y; v[2]=a.z; v[3]=a.w; v[4]=c.x; v[5]=c.y; v[6]=c.z; v[7]=c.w;
        } else if (k0 == 256) {
            v[0] = ti[(size_t)b * T_ + t];
        }
        __half2 h[4];
#pragma unroll
        for (int j = 0; j < 4; j++) h[j] = __floats2half2_rn(v[2 * j], v[2 * j + 1]);
        *(uint4*)(g_xh + (size_t)row * KIN + k0) = *(uint4*)h;
    } else if (bid < PBX + PBW3) {
        int idx = (bid - PBX) * 256 + tid;
        const float* p = W_hh + (size_t)idx * 8;
        float4 a = *(const float4*)p, c = *(const float4*)(p + 4);
        __half2 h[4] = { __floats2half2_rn(a.x, a.y), __floats2half2_rn(a.z, a.w),
                         __floats2half2_rn(c.x, c.y), __floats2half2_rn(c.z, c.w) };
        *(uint4*)(g_w3 + (size_t)idx * 8) = *(uint4*)h;
    } else if (bid < PBX + PBW3 + PBW) {
        int idx = (bid - PBX - PBW3) * 256 + tid;
        int k8 = idx % 40; size_t g = idx / 40;
        int k0 = k8 * 8;
        __half hv[8];
#pragma unroll
        for (int j = 0; j < 8; j++) {
            int k = k0 + j;
            hv[j] = (k < DIN) ? __float2half_rn(W_ih[g * DIN + k]) : __float2half_rn(0.0f);
        }
        *(uint4*)(g_wih + g * KIN + k0) = *(uint4*)hv;
    } else {
        int idx = (bid - PBX - PBW3 - PBW) * 256 + tid;
        float4 z4 = {0.f, 0.f, 0.f, 0.f};
        *(float4*)(g_hf[0] + (size_t)idx * 8) = z4;
        *(float4*)(g_hf[0] + (size_t)idx * 8 + 4) = z4;
        uint4 zu = {0u, 0u, 0u, 0u};
        *(uint4*)(g_hh[0] + (size_t)idx * 8) = zu;
        if (idx < 64) g_bars[idx] = 0u;
    }
}
__global__ void bar_zero() { if (threadIdx.x < 64) g_bars[threadIdx.x] = 0u; }

// ---------------- gi GEMM: W_ih-resident (unchanged, proven) ----------------
__global__ __launch_bounds__(256, 2) void gi_gemm4(const float* __restrict__ b_ih,
                                                   const float* __restrict__ b_hh) {
    extern __shared__ char smc[];
    uint32_t sb = smem_u32(smc);
    uint32_t ast = sb + GI_WSM;
    const int tid = threadIdx.x, lane = tid & 31, wid = tid >> 5;
    const int wm = (wid >> 2) * 32;
    const int wn8 = (wid & 3) * 8;
    const int g4 = lane >> 2, tig = lane & 3;
    const int ni = blockIdx.x, n0 = ni * 32;
    const size_t mbase = (size_t)blockIdx.y * (M_REP * 64);

    {
#pragma unroll 1
        for (int i = tid; i < 5 * 96 * 8; i += 256) {
            int chunk = i / 768, rem = i % 768;
            int rr = rem >> 3, c = rem & 7;
            int grow = (rr >> 5) * H_ + n0 + (rr & 31);
            uint32_t dst = sb + (uint32_t)(chunk * WCH + rr * 128 + ((c ^ (rr & 7)) << 4));
            cpa16(dst, g_wih + (size_t)grow * KIN + chunk * 64 + c * 8);
        }
        cpcommit(); cpwait0();
        __syncthreads();
    }

    const int arow0 = wm + (lane & 15);
    const int acsel = (lane >> 4);
    const int browA = ((lane < 16) ? 0 : 32) + wn8 + (lane & 7);
    const int browC = 64 + wn8 + (lane & 7);
    const int bcsel = (lane >> 3) & 1;

    const int gcol = n0 + wn8 + 2 * tig;
    float2 biasr = { b_ih[gcol] + b_hh[gcol], b_ih[gcol + 1] + b_hh[gcol + 1] };
    float2 biasz = { b_ih[H_ + gcol] + b_hh[H_ + gcol], b_ih[H_ + gcol + 1] + b_hh[H_ + gcol + 1] };
    float2 biasn = { b_ih[2 * H_ + gcol], b_ih[2 * H_ + gcol + 1] };

    auto issueA = [&](int s) {
        int rep = s / 5, chunk = s - rep * 5;
        uint32_t ab = ast + (uint32_t)((s & 3) * AST);
        const __half* Ag = g_xh + (mbase + (size_t)rep * 64) * KIN + chunk * 64;
#pragma unroll
        for (int i = 0; i < 2; i++) {
            int f = tid + 256 * i, r = f >> 3, c = f & 7;
            cpa16(ab + (uint32_t)(r * 128 + ((c ^ (r & 7)) << 4)),
                  Ag + (size_t)r * KIN + c * 8);
        }
        cpcommit();
    };

    float acc[2][3][4];
#pragma unroll
    for (int i = 0; i < 2; i++)
#pragma unroll
        for (int j = 0; j < 3; j++)
#pragma unroll
            for (int e = 0; e < 4; e++) acc[i][j][e] = 0.f;

    issueA(0); issueA(1); issueA(2);
#pragma unroll 1
    for (int s = 0; s < GI_NSTG; s++) {
        cpwait2();
        __syncthreads();
        int rep = s / 5, chunk = s - rep * 5;
        uint32_t ab = ast + (uint32_t)((s & 3) * AST);
        uint32_t wb = sb + (uint32_t)(chunk * WCH);
#pragma unroll
        for (int g = 0; g < 4; g++) {
            uint32_t A0[4], A1[4], B4[4], B2[2];
            {
                int c = 2 * g + acsel;
                int r0 = arow0, r1 = arow0 + 16;
                LDSM4(A0[0], A0[1], A0[2], A0[3], ab + (uint32_t)(r0 * 128 + ((c ^ (r0 & 7)) << 4)));
                LDSM4(A1[0], A1[1], A1[2], A1[3], ab + (uint32_t)(r1 * 128 + ((c ^ (r1 & 7)) << 4)));
            }
            {
                int c = 2 * g + bcsel;
                LDSM4(B4[0], B4[1], B4[2], B4[3], wb + (uint32_t)(browA * 128 + ((c ^ (browA & 7)) << 4)));
                LDSM2(B2[0], B2[1], wb + (uint32_t)(browC * 128 + ((c ^ (browC & 7)) << 4)));
            }
            mma_f16(acc[0][0], A0[0], A0[1], A0[2], A0[3], B4[0], B4[1]);
            mma_f16(acc[1][0], A1[0], A1[1], A1[2], A1[3], B4[0], B4[1]);
            mma_f16(acc[0][1], A0[0], A0[1], A0[2], A0[3], B4[2], B4[3]);
            mma_f16(acc[1][1], A1[0], A1[1], A1[2], A1[3], B4[2], B4[3]);
            mma_f16(acc[0][2], A0[0], A0[1], A0[2], A0[3], B2[0], B2[1]);
            mma_f16(acc[1][2], A1[0], A1[1], A1[2], A1[3], B2[0], B2[1]);
        }
        if (s + 3 < GI_NSTG) issueA(s + 3); else cpcommit();

        if (chunk == 4) {
            size_t rowbase = mbase + (size_t)rep * 64;
#pragma unroll
            for (int mt = 0; mt < 2; mt++)
#pragma unroll
                for (int rh = 0; rh < 2; rh++) {
                    size_t row = rowbase + wm + mt * 16 + g4 + 8 * rh;
                    __half* gp = g_gi + row * G_ + gcol;
                    *(__half2*)(gp)          = __floats2half2_rn(acc[mt][0][2 * rh] + biasr.x,
                                                                 acc[mt][0][2 * rh + 1] + biasr.y);
                    *(__half2*)(gp + H_)     = __floats2half2_rn(acc[mt][1][2 * rh] + biasz.x,
                                                                 acc[mt][1][2 * rh + 1] + biasz.y);
                    *(__half2*)(gp + 2 * H_) = __floats2half2_rn(acc[mt][2][2 * rh] + biasn.x,
                                                                 acc[mt][2][2 * rh + 1] + biasn.y);
                }
#pragma unroll
            for (int i = 0; i < 2; i++)
#pragma unroll
                for (int j = 0; j < 3; j++)
#pragma unroll
                    for (int e = 0; e < 4; e++) acc[i][j][e] = 0.f;
        }
    }
    cpwait0();
}

// ---------------- persistent GRU recurrence: dual wg pipelines, BK=128, 2-buffer ----------------
__global__ __launch_bounds__(256, 1) void gru_persist() {
    extern __shared__ char smc[];
    uint32_t sb = smem_u32(smc);
    const int tid = threadIdx.x, lane = tid & 31, wid = tid >> 5;
    const int wg = tid >> 7;
    const int wn8 = (wid & 3) * 8;
    const int g4 = lane >> 2, tig = lane & 3;
    const int mi = blockIdx.x >> 5, ni = blockIdx.x & 31;
    const int n0 = ni * 32;
    uint32_t ast = sb + W_SM + (uint32_t)wg * (2 * ASTP);
    unsigned* barp = &g_bars[mi * 16];
    const int bar_id = wg + 1;

    // ---- load W_hh slice once (CTA-wide) ----
    {
#pragma unroll 1
        for (int i = tid; i < 12288; i += 256) {
            int rr = i >> 7, cg = i & 127;
            int s = cg >> 3, c = cg & 7;
            int grow = (rr >> 5) * H_ + n0 + (rr & 31);
            uint32_t dst = sb + (uint32_t)(s * WCH + rr * 128 + ((c ^ (rr & 7)) << 4));
            cpa16(dst, g_w3 + (size_t)grow * H_ + s * 64 + c * 8);
        }
        cpcommit(); cpwait0();
        __syncthreads();
    }

    const int ltid = tid & 127;
    const int arow0 = lane & 15;
    const int acsel = (lane >> 4);
    const int browA = ((lane < 16) ? 0 : 32) + wn8 + (lane & 7);
    const int browC = 64 + wn8 + (lane & 7);
    const int bcsel = (lane >> 3) & 1;

    const int col2 = n0 + wn8 + 2 * tig;
    const int mrow0 = mi * 64 + wg * 32;

    float hc[8];
#pragma unroll
    for (int j = 0; j < 8; j++) hc[j] = 0.f;

    float2 gir[4], giz[4], gin[4];
#pragma unroll
    for (int q = 0; q < 4; q++) {
        int row = mrow0 + (q >> 1) * 16 + g4 + 8 * (q & 1);
        const __half* p = g_gi + (size_t)row * G_ + col2;
        gir[q] = __half22float2(*(const __half2*)(p));
        giz[q] = __half22float2(*(const __half2*)(p + H_));
        gin[q] = __half22float2(*(const __half2*)(p + 2 * H_));
    }

#pragma unroll 1
    for (int t = 0; t < T_; t++) {
        if (t > 0) {
            if (ltid == 0) {
                unsigned v; const unsigned tgt = 64u * (unsigned)t;
                do { asm volatile("ld.acquire.gpu.global.u32 %0, [%1];" : "=r"(v) : "l"(barp)); } while (v < tgt);
            }
            WGBAR(bar_id);
        }

        const __half* __restrict__ Ah = g_hh[t & 1] + (size_t)mrow0 * H_;

        float acc[2][3][4];
#pragma unroll
        for (int i = 0; i < 2; i++)
#pragma unroll
            for (int j = 0; j < 3; j++)
#pragma unroll
                for (int e = 0; e < 4; e++) acc[i][j][e] = 0.f;

        // BK=128 stage: 2 sub-chunks of 32 rows x 128B. 512 x 16B per stage, 4/thread.
        auto issueA = [&](int s) {
            uint32_t ab = ast + (uint32_t)((s & 1) * ASTP);
            int kc = s * 128;
#pragma unroll
            for (int i = 0; i < 4; i++) {
                int f = ltid + 128 * i;
                int r = f >> 4, cc = f & 15;
                int sub = cc >> 3, c = cc & 7;
                cpa16(ab + (uint32_t)(sub * 4096 + r * 128 + ((c ^ (r & 7)) << 4)),
                      Ah + (size_t)r * H_ + kc + sub * 64 + c * 8);
            }
            cpcommit();
        };
        issueA(0);
#pragma unroll 1
        for (int s = 0; s < 8; s++) {
            cpwait0();
            WGBAR(bar_id);              // all fills landed; compute(s-1) done by all -> buf (s+1)&1 free
            if (s + 1 < 8) issueA(s + 1);
            uint32_t ab = ast + (uint32_t)((s & 1) * ASTP);
#pragma unroll
            for (int g = 0; g < 8; g++) {
                int sub = g >> 2, gg = g & 3;
                uint32_t abx = ab + (uint32_t)(sub * 4096);
                uint32_t wb = sb + (uint32_t)((2 * s + sub) * WCH);
                uint32_t A0[4], A1[4], B4[4], B2[2];
                {
                    int c = 2 * gg + acsel;
                    int r0 = arow0, r1 = arow0 + 16;
                    LDSM4(A0[0], A0[1], A0[2], A0[3], abx + (uint32_t)(r0 * 128 + ((c ^ (r0 & 7)) << 4)));
                    LDSM4(A1[0], A1[1], A1[2], A1[3], abx + (uint32_t)(r1 * 128 + ((c ^ (r1 & 7)) << 4)));
                }
                {
                    int c = 2 * gg + bcsel;
                    LDSM4(B4[0], B4[1], B4[2], B4[3], wb + (uint32_t)(browA * 128 + ((c ^ (browA & 7)) << 4)));
                    LDSM2(B2[0], B2[1], wb + (uint32_t)(browC * 128 + ((c ^ (browC & 7)) << 4)));
                }
                mma_f16(acc[0][0], A0[0], A0[1], A0[2], A0[3], B4[0], B4[1]);
                mma_f16(acc[1][0], A1[0], A1[1], A1[2], A1[3], B4[0], B4[1]);
                mma_f16(acc[0][1], A0[0], A0[1], A0[2], A0[3], B4[2], B4[3]);
                mma_f16(acc[1][1], A1[0], A1[1], A1[2], A1[3], B4[2], B4[3]);
                mma_f16(acc[0][2], A0[0], A0[1], A0[2], A0[3], B2[0], B2[1]);
                mma_f16(acc[1][2], A1[0], A1[1], A1[2], A1[3], B2[0], B2[1]);
            }
        }

        // ---- register-resident gate epilogue ----
        {
            __half* __restrict__ hxB = g_hh[(t + 1) & 1];
#pragma unroll
            for (int q = 0; q < 4; q++) {
                int mt = q >> 1, rh = q & 1;
                int row = mrow0 + mt * 16 + g4 + 8 * rh;
                float o0, o1;
                {
                    float rr = fsig(gir[q].x + acc[mt][0][2 * rh]);
                    float zz = fsig(giz[q].x + acc[mt][1][2 * rh]);
                    float nn = ftanh_(gin[q].x + rr * acc[mt][2][2 * rh]);
                    o0 = (1.0f - zz) * nn + zz * hc[2 * q];
                }
                {
                    float rr = fsig(gir[q].y + acc[mt][0][2 * rh + 1]);
                    float zz = fsig(giz[q].y + acc[mt][1][2 * rh + 1]);
                    float nn = ftanh_(gin[q].y + rr * acc[mt][2][2 * rh + 1]);
                    o1 = (1.0f - zz) * nn + zz * hc[2 * q + 1];
                }
                hc[2 * q] = o0; hc[2 * q + 1] = o1;
                *(__half2*)(hxB + (size_t)row * H_ + col2) = __floats2half2_rn(o0, o1);
                if (t == T_ - 1) {
                    float2 ov = { o0, o1 };
                    *(float2*)(g_hf[0] + (size_t)row * H_ + col2) = ov;
                }
            }
        }

        // ---- publish h(t+1) (wg-granular), then prefetch gi(t+1) ----
        WGBAR(bar_id);
        if (ltid == 0)
            asm volatile("red.release.gpu.global.add.u32 [%0], 1;" :: "l"(barp) : "memory");

        if (t + 1 < T_) {
            const __half* __restrict__ gi_t = g_gi + (size_t)(t + 1) * B_ * G_;
#pragma unroll
            for (int q = 0; q < 4; q++) {
                int row = mrow0 + (q >> 1) * 16 + g4 + 8 * (q & 1);
                const __half* p = gi_t + (size_t)row * G_ + col2;
                gir[q] = __half22float2(*(const __half2*)(p));
                giz[q] = __half22float2(*(const __half2*)(p + H_));
                gin[q] = __half22float2(*(const __half2*)(p + 2 * H_));
            }
        }
    }
}

// ---------------- output head ----------------
__global__ void out_gemm(const float* __restrict__ Wout, const float* __restrict__ bout, float* __restrict__ out) {
    const int b = blockIdx.x;
    const int wid = threadIdx.x >> 5, lane = threadIdx.x & 31;
    const int o0 = blockIdx.y * 32 + wid * 4;
    const float* __restrict__ h = g_hf[0] + (size_t)b * H_;
    float acc[4] = {0.f, 0.f, 0.f, 0.f};
#pragma unroll
    for (int kk = 0; kk < 8; kk++) {
        int k = kk * 128 + lane * 4;
        float4 hv = *(const float4*)(h + k);
#pragma unroll
        for (int j = 0; j < 4; j++) {
            float4 w = *(const float4*)(Wout + (size_t)(o0 + j) * H_ + k);
            acc[j] += hv.x * w.x + hv.y * w.y + hv.z * w.z + hv.w * w.w;
        }
    }
#pragma unroll
    for (int j = 0; j < 4; j++) {
        float v = acc[j];
#pragma unroll
        for (int s = 16; s > 0; s >>= 1) v += __shfl_xor_sync(0xffffffffu, v, s);
        if (lane == 0) out[(size_t)b * O_ + o0 + j] = v + bout[o0 + j];
    }
}

// ---------------- launch ----------------
extern "C" void kernel_launch(void* const* d_in, const int* in_sizes, int n_in,
                              void* d_out, int out_size) {
    const float* x     = (const float*)d_in[0];
    const float* mask  = (const float*)d_in[1];
    const float* ti    = (const float*)d_in[2];
    const float* W_ih  = (const float*)d_in[3];
    const float* W_hh  = (const float*)d_in[4];
    const float* b_ih  = (const float*)d_in[5];
    const float* b_hh  = (const float*)d_in[6];
    const float* W_out = (const float*)d_in[7];
    const float* b_out = (const float*)d_in[8];
    float* out = (float*)d_out;

    static int smem_set = 0;
    if (!smem_set) {
        cudaFuncSetAttribute(gi_gemm4, cudaFuncAttributeMaxDynamicSharedMemorySize, GI_SMEM2);
        cudaFuncSetAttribute(gru_persist, cudaFuncAttributeMaxDynamicSharedMemorySize, P_SMEM);
        smem_set = 1;
    }

    pack_fused<<<PBX + PBW3 + PBW + PBZ, 256>>>(x, mask, ti, W_ih, W_hh);          // 0
    gi_gemm4<<<dim3(32, (T_ * B_) / (M_REP * 64)), 256, GI_SMEM2>>>(b_ih, b_hh);   // 1
    bar_zero<<<1, 64>>>();                                                          // 2
    gru_persist<<<128, 256, P_SMEM>>>();                                            // 3 (profiled)
    out_gemm<<<dim3(B_, O_ / 32), 256>>>(W_out, b_out, out);                        // 4
}